// round 10
// baseline (speedup 1.0000x reference)
#include <cuda_runtime.h>
#include <cuda_bf16.h>
#include <cuda_fp8.h>
#include <math.h>
#include <stdint.h>

// NNclrInfoNCECriterion on GB300 (compute_103 PTX -> legacy mma.sync path).
// Stage 1: e4m3 fp8 mma.sync sim GEMM (emb*4, queue*64), per-thread top-2 ->
//          CTA top-4 candidates -> exact fp32 rescore -> argmax.
// Stage 2: bf16 mma.sync logits GEMM + fp32 online LSE; exact fp32 diagonal.

#define B_TOT 4096
#define HALF  2048
#define DDIM  256
#define QTOT  65536
#define QS    32
#define QCHUNK (QTOT/QS)     // 2048
#define NTILE  (QCHUNK/128)  // 16 col-tiles per CTA
#define CS 4
#define NCOL (HALF/CS)       // 512
#define NTILE_LOG (NCOL/128) // 4
#define INV_T 10.0f
#define SCALE_E 4.0f
#define SCALE_Q 64.0f
#define RS_MARGIN 100.0f     // in scaled units (scale = 256); ~0.39 unscaled ~ 7.5 sigma

// ---------------- scratch globals ----------------
__device__ uint8_t g_qf8[(size_t)QTOT * DDIM];
__device__ uint8_t g_ef8[(size_t)B_TOT * DDIM];
__device__ __nv_bfloat16 g_qhi[(size_t)QTOT * DDIM];
__device__ __nv_bfloat16 g_phi[(size_t)B_TOT * DDIM];
__device__ float g_c4val[(size_t)B_TOT * 4 * QS];
__device__ int   g_c4idx[(size_t)B_TOT * 4 * QS];
__device__ int   g_gidx[B_TOT];
__device__ float g_lsem[2 * HALF * CS];
__device__ float g_lses[2 * HALF * CS];
__device__ float g_rowloss[2 * HALF];

// ---------------- helpers ----------------
__device__ __forceinline__ uint32_t smem_to_u32(const void* p) {
    uint32_t a;
    asm("{ .reg .u64 t; cvta.to.shared.u64 t, %1; cvt.u32.u64 %0, t; }" : "=r"(a) : "l"(p));
    return a;
}
__device__ __forceinline__ void cp_async16(uint32_t dst, const void* src) {
    asm volatile("cp.async.cg.shared.global [%0], [%1], 16;" :: "r"(dst), "l"(src) : "memory");
}
#define CP_COMMIT() asm volatile("cp.async.commit_group;" ::: "memory")
#define CP_WAIT0()  asm volatile("cp.async.wait_group 0;" ::: "memory")

__device__ __forceinline__ void ldsm_x4(uint32_t& r0, uint32_t& r1, uint32_t& r2, uint32_t& r3,
                                        uint32_t addr) {
    asm volatile("ldmatrix.sync.aligned.m8n8.x4.shared.b16 {%0,%1,%2,%3}, [%4];"
                 : "=r"(r0), "=r"(r1), "=r"(r2), "=r"(r3) : "r"(addr));
}
__device__ __forceinline__ void mma16816(float& d0, float& d1, float& d2, float& d3,
                                         uint32_t a0, uint32_t a1, uint32_t a2, uint32_t a3,
                                         uint32_t b0, uint32_t b1) {
    asm volatile("mma.sync.aligned.m16n8k16.row.col.f32.bf16.bf16.f32 "
                 "{%0,%1,%2,%3}, {%4,%5,%6,%7}, {%8,%9}, {%0,%1,%2,%3};"
                 : "+f"(d0), "+f"(d1), "+f"(d2), "+f"(d3)
                 : "r"(a0), "r"(a1), "r"(a2), "r"(a3), "r"(b0), "r"(b1));
}
__device__ __forceinline__ void mma_fp8(float& d0, float& d1, float& d2, float& d3,
                                        uint32_t a0, uint32_t a1, uint32_t a2, uint32_t a3,
                                        uint32_t b0, uint32_t b1) {
    asm volatile("mma.sync.aligned.m16n8k32.row.col.f32.e4m3.e4m3.f32 "
                 "{%0,%1,%2,%3}, {%4,%5,%6,%7}, {%8,%9}, {%0,%1,%2,%3};"
                 : "+f"(d0), "+f"(d1), "+f"(d2), "+f"(d3)
                 : "r"(a0), "r"(a1), "r"(a2), "r"(a3), "r"(b0), "r"(b1));
}
// bf16 tile swizzle (512 B rows)
__device__ __forceinline__ uint32_t sw(uint32_t row, uint32_t kb) {
    return row * 512u + (kb ^ ((row & 7u) << 4));
}
// fp8 tile swizzle (256 B rows, 16 x 16B chunks per row)
__device__ __forceinline__ uint32_t sw8(uint32_t row, uint32_t chunk) {
    return row * 256u + ((chunk ^ (row & 7u)) << 4);
}

// ============================================================
// conversions
// ============================================================
__global__ void to_bf16_kernel(const float* __restrict__ src,
                               __nv_bfloat16* __restrict__ dst, int n4)
{
    int i = blockIdx.x * blockDim.x + threadIdx.x;
    if (i < n4) {
        float4 v = ((const float4*)src)[i];
        ((__nv_bfloat162*)dst)[2 * i]     = __floats2bfloat162_rn(v.x, v.y);
        ((__nv_bfloat162*)dst)[2 * i + 1] = __floats2bfloat162_rn(v.z, v.w);
    }
}
__global__ void emb_to_fp8_kernel(const float* __restrict__ src,
                                  uint8_t* __restrict__ dst, int n4)
{
    int i = blockIdx.x * blockDim.x + threadIdx.x;
    if (i < n4) {
        float4 v = ((const float4*)src)[i];
        uchar4 o;
        o.x = __nv_cvt_float_to_fp8(v.x * SCALE_E, __NV_SATFINITE, __NV_E4M3);
        o.y = __nv_cvt_float_to_fp8(v.y * SCALE_E, __NV_SATFINITE, __NV_E4M3);
        o.z = __nv_cvt_float_to_fp8(v.z * SCALE_E, __NV_SATFINITE, __NV_E4M3);
        o.w = __nv_cvt_float_to_fp8(v.w * SCALE_E, __NV_SATFINITE, __NV_E4M3);
        ((uchar4*)dst)[i] = o;
    }
}
// queue: one read -> bf16 (for logits gather) + fp8 (for argmax)
__global__ void queue_conv_kernel(const float* __restrict__ src,
                                  __nv_bfloat16* __restrict__ bh,
                                  uint8_t* __restrict__ f8, int n4)
{
    int i = blockIdx.x * blockDim.x + threadIdx.x;
    if (i < n4) {
        float4 v = ((const float4*)src)[i];
        ((__nv_bfloat162*)bh)[2 * i]     = __floats2bfloat162_rn(v.x, v.y);
        ((__nv_bfloat162*)bh)[2 * i + 1] = __floats2bfloat162_rn(v.z, v.w);
        uchar4 o;
        o.x = __nv_cvt_float_to_fp8(v.x * SCALE_Q, __NV_SATFINITE, __NV_E4M3);
        o.y = __nv_cvt_float_to_fp8(v.y * SCALE_Q, __NV_SATFINITE, __NV_E4M3);
        o.z = __nv_cvt_float_to_fp8(v.z * SCALE_Q, __NV_SATFINITE, __NV_E4M3);
        o.w = __nv_cvt_float_to_fp8(v.w * SCALE_Q, __NV_SATFINITE, __NV_E4M3);
        ((uchar4*)f8)[i] = o;
    }
}

// ============================================================
// Kernel 1: fp8 mma.sync sim GEMM + per-thread top-2 -> CTA top-4.
// 512 threads, 16 warps (4x4), warp tile 32x32, K=256 (8 k32-steps).
// A fp8 smem-resident (32KB); B fp8 double-buffered (2x32KB) via cp.async.
// ============================================================
__global__ __launch_bounds__(512, 1)
void argmax_mma_kernel()
{
    extern __shared__ char smem[];
    const uint32_t sb   = smem_to_u32(smem);
    const uint32_t as8  = (sb + 1023u) & ~1023u;   // A: 32KB
    const uint32_t bs8  = as8 + 32768u;            // B: 2 x 32KB

    const int tid  = threadIdx.x;
    const int lane = tid & 31;
    const int w    = tid >> 5;
    const int wm   = w >> 2;
    const int wn   = w & 3;
    const int rowBase = blockIdx.x * 128;
    const int qBase   = blockIdx.y * QCHUNK;

    // ---- async load A (128x256 fp8) + B tile 0 ----
    #pragma unroll
    for (int i = 0; i < 4; ++i) {
        int c = i * 512 + tid;                 // 16B chunk id, 0..2047
        uint32_t row = (uint32_t)(c >> 4), ch = (uint32_t)(c & 15);
        cp_async16(as8 + sw8(row, ch),
                   g_ef8 + (size_t)(rowBase + row) * DDIM + ch * 16);
    }
    #pragma unroll
    for (int i = 0; i < 4; ++i) {
        int c = i * 512 + tid;
        uint32_t row = (uint32_t)(c >> 4), ch = (uint32_t)(c & 15);
        cp_async16(bs8 + sw8(row, ch),
                   g_qf8 + (size_t)(qBase + row) * DDIM + ch * 16);
    }
    CP_COMMIT();
    CP_WAIT0();
    __syncthreads();

    float tv[4][2];
    int   tix[4][2];
    #pragma unroll
    for (int s = 0; s < 4; ++s) {
        tv[s][0] = -INFINITY; tv[s][1] = -INFINITY;
        tix[s][0] = 0x7fffffff; tix[s][1] = 0x7fffffff;
    }

    for (int ct = 0; ct < NTILE; ++ct) {
        // prefetch next B tile
        if (ct + 1 < NTILE) {
            const uint32_t nbuf = bs8 + (uint32_t)((ct + 1) & 1) * 32768u;
            #pragma unroll
            for (int i = 0; i < 4; ++i) {
                int c = i * 512 + tid;
                uint32_t row = (uint32_t)(c >> 4), ch = (uint32_t)(c & 15);
                cp_async16(nbuf + sw8(row, ch),
                           g_qf8 + (size_t)(qBase + (ct + 1) * 128 + row) * DDIM + ch * 16);
            }
            CP_COMMIT();
        }

        const uint32_t bbuf = bs8 + (uint32_t)(ct & 1) * 32768u;
        float acc[2][4][4];
        #pragma unroll
        for (int mi = 0; mi < 2; ++mi)
            #pragma unroll
            for (int ni = 0; ni < 4; ++ni)
                #pragma unroll
                for (int d = 0; d < 4; ++d) acc[mi][ni][d] = 0.0f;

        // fragment double-buffer across the 8 k32-steps
        uint32_t a[2][2][4], b[2][4][2];
        // load step 0
        #pragma unroll
        for (int mi = 0; mi < 2; ++mi) {
            uint32_t row = (uint32_t)(wm * 32 + mi * 16 + (lane & 15));
            uint32_t ch  = (uint32_t)((lane >> 4));
            ldsm_x4(a[0][mi][0], a[0][mi][1], a[0][mi][2], a[0][mi][3], as8 + sw8(row, ch));
        }
        #pragma unroll
        for (int np = 0; np < 2; ++np) {
            uint32_t col = (uint32_t)(wn * 32 + np * 16 + (lane & 7) + ((lane >> 4) & 1) * 8);
            uint32_t ch  = (uint32_t)(((lane >> 3) & 1));
            uint32_t r0, r1, r2, r3;
            ldsm_x4(r0, r1, r2, r3, bbuf + sw8(col, ch));
            b[0][2 * np][0] = r0; b[0][2 * np][1] = r1;
            b[0][2 * np + 1][0] = r2; b[0][2 * np + 1][1] = r3;
        }

        #pragma unroll
        for (int kq = 0; kq < 8; ++kq) {
            const int cur = kq & 1;
            if (kq < 7) {
                const int nk = kq + 1;
                #pragma unroll
                for (int mi = 0; mi < 2; ++mi) {
                    uint32_t row = (uint32_t)(wm * 32 + mi * 16 + (lane & 15));
                    uint32_t ch  = (uint32_t)(nk * 2 + (lane >> 4));
                    ldsm_x4(a[cur ^ 1][mi][0], a[cur ^ 1][mi][1],
                            a[cur ^ 1][mi][2], a[cur ^ 1][mi][3], as8 + sw8(row, ch));
                }
                #pragma unroll
                for (int np = 0; np < 2; ++np) {
                    uint32_t col = (uint32_t)(wn * 32 + np * 16 + (lane & 7) + ((lane >> 4) & 1) * 8);
                    uint32_t ch  = (uint32_t)(nk * 2 + ((lane >> 3) & 1));
                    uint32_t r0, r1, r2, r3;
                    ldsm_x4(r0, r1, r2, r3, bbuf + sw8(col, ch));
                    b[cur ^ 1][2 * np][0] = r0; b[cur ^ 1][2 * np][1] = r1;
                    b[cur ^ 1][2 * np + 1][0] = r2; b[cur ^ 1][2 * np + 1][1] = r3;
                }
            }
            #pragma unroll
            for (int mi = 0; mi < 2; ++mi)
                #pragma unroll
                for (int ni = 0; ni < 4; ++ni)
                    mma_fp8(acc[mi][ni][0], acc[mi][ni][1], acc[mi][ni][2], acc[mi][ni][3],
                            a[cur][mi][0], a[cur][mi][1], a[cur][mi][2], a[cur][mi][3],
                            b[cur][ni][0], b[cur][ni][1]);
        }

        // epilogue: approx top-2 per owned row-slot
        const int colT = qBase + ct * 128 + wn * 32 + (lane & 3) * 2;
        #pragma unroll
        for (int mi = 0; mi < 2; ++mi)
            #pragma unroll
            for (int ni = 0; ni < 4; ++ni)
                #pragma unroll
                for (int d = 0; d < 4; ++d) {
                    float v = acc[mi][ni][d];
                    int   c = colT + ni * 8 + (d & 1);
                    int   s = mi * 2 + (d >> 1);
                    if (v > tv[s][0]) {
                        tv[s][1] = tv[s][0]; tix[s][1] = tix[s][0];
                        tv[s][0] = v;        tix[s][0] = c;
                    } else if (v > tv[s][1]) {
                        tv[s][1] = v;        tix[s][1] = c;
                    }
                }

        CP_WAIT0();
        __syncthreads();
    }

    // ---- CTA top-4 reduce (reuse A+B smem): 16 contributors x 2 per row ----
    float* sval = (float*)(smem + (as8 - sb));
    int*   sidx = (int*)(sval + 128 * 32);
    const int own = wn * 4 + (lane & 3);
    #pragma unroll
    for (int s = 0; s < 4; ++s) {
        int rowL = wm * 32 + (s >> 1) * 16 + (s & 1) * 8 + (lane >> 2);
        sval[rowL * 32 + own * 2 + 0] = tv[s][0];
        sval[rowL * 32 + own * 2 + 1] = tv[s][1];
        sidx[rowL * 32 + own * 2 + 0] = tix[s][0];
        sidx[rowL * 32 + own * 2 + 1] = tix[s][1];
    }
    __syncthreads();
    if (tid < 128) {
        float t0 = -INFINITY, t1 = -INFINITY, t2 = -INFINITY, t3 = -INFINITY;
        int   j0 = 0x7fffffff, j1 = 0x7fffffff, j2 = 0x7fffffff, j3 = 0x7fffffff;
        #pragma unroll
        for (int t = 0; t < 32; ++t) {
            float v = sval[tid * 32 + t];
            int   i = sidx[tid * 32 + t];
            if (v > t0)      { t3=t2; j3=j2; t2=t1; j2=j1; t1=t0; j1=j0; t0=v; j0=i; }
            else if (v > t1) { t3=t2; j3=j2; t2=t1; j2=j1; t1=v; j1=i; }
            else if (v > t2) { t3=t2; j3=j2; t2=v; j2=i; }
            else if (v > t3) { t3=v; j3=i; }
        }
        size_t o = (size_t)(rowBase + tid) * (4 * QS) + blockIdx.y * 4;
        g_c4val[o + 0] = t0; g_c4idx[o + 0] = j0;
        g_c4val[o + 1] = t1; g_c4idx[o + 1] = j1;
        g_c4val[o + 2] = t2; g_c4idx[o + 2] = j2;
        g_c4val[o + 3] = t3; g_c4idx[o + 3] = j3;
    }
}

// ============================================================
// Kernel 2: exact fp32 rescore of 128 candidates -> g_gidx.
// One warp per row; threshold = approx_max - RS_MARGIN (scaled units).
// ============================================================
__global__ void rescore_kernel(const float* __restrict__ emb,
                               const float* __restrict__ queue)
{
    int warp = (blockIdx.x * blockDim.x + threadIdx.x) >> 5;
    int lane = threadIdx.x & 31;
    if (warp >= B_TOT) return;

    size_t o = (size_t)warp * (4 * QS);
    float v[4]; int ix[4];
    #pragma unroll
    for (int j = 0; j < 4; ++j) {
        v[j]  = g_c4val[o + j * 32 + lane];
        ix[j] = g_c4idx[o + j * 32 + lane];
    }

    float m = fmaxf(fmaxf(v[0], v[1]), fmaxf(v[2], v[3]));
    #pragma unroll
    for (int sh = 16; sh; sh >>= 1) m = fmaxf(m, __shfl_xor_sync(0xffffffffu, m, sh));
    const float thr = m - RS_MARGIN;

    const float4* e4 = (const float4*)(emb + (size_t)warp * DDIM);
    float bv = -INFINITY; int bi = 0x7fffffff;
    #pragma unroll
    for (int j = 0; j < 4; ++j) {
        if (v[j] >= thr) {
            const float4* q4 = (const float4*)(queue + (size_t)ix[j] * DDIM);
            float acc = 0.0f;
            #pragma unroll 8
            for (int k = 0; k < 64; ++k) {
                float4 a = e4[k], b = q4[k];
                acc = fmaf(a.x, b.x, acc); acc = fmaf(a.y, b.y, acc);
                acc = fmaf(a.z, b.z, acc); acc = fmaf(a.w, b.w, acc);
            }
            if (acc > bv || (acc == bv && ix[j] < bi)) { bv = acc; bi = ix[j]; }
        }
    }
    #pragma unroll
    for (int sh = 16; sh; sh >>= 1) {
        float ov = __shfl_xor_sync(0xffffffffu, bv, sh);
        int   oi = __shfl_xor_sync(0xffffffffu, bi, sh);
        if (ov > bv || (ov == bv && oi < bi)) { bv = ov; bi = oi; }
    }
    if (lane == 0) g_gidx[warp] = bi;
}

// ============================================================
// Kernel 3: bf16 mma.sync logits GEMM + fp32 online logsumexp partials.
// grid (16 row-tiles, CS colgroups, 2 dirs); 256 thr, 8 warps (4x2), tile 32x64.
// ============================================================
__global__ __launch_bounds__(256, 1)
void logits_mma_kernel()
{
    extern __shared__ char smem[];
    const uint32_t sb   = smem_to_u32(smem);
    const uint32_t as32 = (sb + 1023u) & ~1023u;
    const uint32_t bs32 = as32 + 65536u;

    const int tid  = threadIdx.x;
    const int lane = tid & 31;
    const int w    = tid >> 5;
    const int wm   = w >> 1;
    const int wn   = w & 1;
    const int dir      = blockIdx.z;
    const int rowBase  = blockIdx.x * 128;
    const int colBase  = blockIdx.y * NCOL;
    const int predBase = (dir == 0) ? HALF : 0;
    const int idxBase  = dir * HALF;

    #pragma unroll
    for (int i = 0; i < 16; ++i) {
        int c = i * 256 + tid;
        uint32_t row = (uint32_t)(c >> 5), k16 = (uint32_t)(c & 31);
        int qi = g_gidx[idxBase + rowBase + (int)row];
        cp_async16(as32 + sw(row, k16 * 16),
                   (const char*)(g_qhi + (size_t)qi * DDIM) + k16 * 16);
    }
    #pragma unroll
    for (int i = 0; i < 16; ++i) {
        int c = i * 256 + tid;
        uint32_t row = (uint32_t)(c >> 5), k16 = (uint32_t)(c & 31);
        cp_async16(bs32 + sw(row, k16 * 16),
                   (const char*)(g_phi + (size_t)(predBase + colBase + row) * DDIM) + k16 * 16);
    }
    CP_COMMIT();
    CP_WAIT0();
    __syncthreads();

    float lm[4], ls[4];
    #pragma unroll
    for (int s = 0; s < 4; ++s) { lm[s] = -INFINITY; ls[s] = 0.0f; }

    for (int ct = 0; ct < NTILE_LOG; ++ct) {
        if (ct + 1 < NTILE_LOG) {
            const uint32_t nbuf = bs32 + (uint32_t)((ct + 1) & 1) * 65536u;
            #pragma unroll
            for (int i = 0; i < 16; ++i) {
                int c = i * 256 + tid;
                uint32_t row = (uint32_t)(c >> 5), k16 = (uint32_t)(c & 31);
                cp_async16(nbuf + sw(row, k16 * 16),
                           (const char*)(g_phi + (size_t)(predBase + colBase + (ct + 1) * 128 + row) * DDIM) + k16 * 16);
            }
            CP_COMMIT();
        }

        const uint32_t bbuf = bs32 + (uint32_t)(ct & 1) * 65536u;
        float acc[2][8][4];
        #pragma unroll
        for (int mi = 0; mi < 2; ++mi)
            #pragma unroll
            for (int ni = 0; ni < 8; ++ni)
                #pragma unroll
                for (int d = 0; d < 4; ++d) acc[mi][ni][d] = 0.0f;

        #pragma unroll
        for (int kf = 0; kf < 16; ++kf) {
            uint32_t a[2][4];
            #pragma unroll
            for (int mi = 0; mi < 2; ++mi) {
                uint32_t row = (uint32_t)(wm * 32 + mi * 16 + (lane & 15));
                uint32_t kb  = (uint32_t)(kf * 32 + (lane >> 4) * 16);
                ldsm_x4(a[mi][0], a[mi][1], a[mi][2], a[mi][3], as32 + sw(row, kb));
            }
            uint32_t b[8][2];
            #pragma unroll
            for (int np = 0; np < 4; ++np) {
                uint32_t col = (uint32_t)(wn * 64 + np * 16 + (lane & 7) + ((lane >> 4) & 1) * 8);
                uint32_t kb  = (uint32_t)(kf * 32 + ((lane >> 3) & 1) * 16);
                uint32_t r0, r1, r2, r3;
                ldsm_x4(r0, r1, r2, r3, bbuf + sw(col, kb));
                b[2 * np][0] = r0; b[2 * np][1] = r1;
                b[2 * np + 1][0] = r2; b[2 * np + 1][1] = r3;
            }
            #pragma unroll
            for (int mi = 0; mi < 2; ++mi)
                #pragma unroll
                for (int ni = 0; ni < 8; ++ni)
                    mma16816(acc[mi][ni][0], acc[mi][ni][1], acc[mi][ni][2], acc[mi][ni][3],
                             a[mi][0], a[mi][1], a[mi][2], a[mi][3], b[ni][0], b[ni][1]);
        }

        #pragma unroll
        for (int mi = 0; mi < 2; ++mi)
            #pragma unroll
            for (int ni = 0; ni < 8; ++ni)
                #pragma unroll
                for (int d = 0; d < 4; ++d) {
                    float x = acc[mi][ni][d] * INV_T;
                    int   s = mi * 2 + (d >> 1);
                    if (x > lm[s]) {
                        ls[s] = ls[s] * expf(lm[s] - x) + 1.0f;
                        lm[s] = x;
                    } else {
                        ls[s] += expf(x - lm[s]);
                    }
                }

        CP_WAIT0();
        __syncthreads();
    }

    float* sM = (float*)(smem + (as32 - sb));
    float* sS = sM + 128 * 8;
    const int cont = wn * 4 + (lane & 3);
    #pragma unroll
    for (int s = 0; s < 4; ++s) {
        int rowL = wm * 32 + (s >> 1) * 16 + (s & 1) * 8 + (lane >> 2);
        sM[rowL * 8 + cont] = lm[s];
        sS[rowL * 8 + cont] = ls[s];
    }
    __syncthreads();
    if (tid < 128) {
        float M = -INFINITY;
        #pragma unroll
        for (int t = 0; t < 8; ++t) M = fmaxf(M, sM[tid * 8 + t]);
        float S = 0.0f;
        #pragma unroll
        for (int t = 0; t < 8; ++t) S += sS[tid * 8 + t] * expf(sM[tid * 8 + t] - M);
        int row = rowBase + tid;
        g_lsem[(size_t)(idxBase + row) * CS + blockIdx.y] = M;
        g_lses[(size_t)(idxBase + row) * CS + blockIdx.y] = S;
    }
}

// ============================================================
// Kernel 4: per-row loss = logsumexp - exact fp32 diagonal logit.
// ============================================================
__global__ void ce_finalize_kernel(const float* __restrict__ queue,
                                   const float* __restrict__ preds)
{
    int warp = (blockIdx.x * blockDim.x + threadIdx.x) >> 5;
    int lane = threadIdx.x & 31;
    #pragma unroll
    for (int rr = 0; rr < 4; ++rr) {
        int ridx = warp * 4 + rr;
        if (ridx >= 2 * HALF) return;
        int dir = ridx >> 11;
        int row = ridx & (HALF - 1);
        int qi  = g_gidx[dir * HALF + row];
        const float* a = queue + (size_t)qi * DDIM;
        const float* b = preds + (size_t)(((dir == 0) ? HALF : 0) + row) * DDIM;
        float p = 0.0f;
        for (int k = lane; k < DDIM; k += 32) p = fmaf(a[k], b[k], p);
        #pragma unroll
        for (int o = 16; o; o >>= 1) p += __shfl_xor_sync(0xffffffffu, p, o);
        if (lane == 0) {
            float M = -INFINITY;
            #pragma unroll
            for (int t = 0; t < CS; ++t) M = fmaxf(M, g_lsem[(size_t)ridx * CS + t]);
            float S = 0.0f;
            #pragma unroll
            for (int t = 0; t < CS; ++t)
                S += g_lses[(size_t)ridx * CS + t] * expf(g_lsem[(size_t)ridx * CS + t] - M);
            float lse = M + logf(S);
            g_rowloss[ridx] = lse - p * INV_T;
        }
    }
}

// ============================================================
// Kernel 5: final reduction -> scalar loss
// ============================================================
__global__ void final_sum_kernel(float* __restrict__ out)
{
    __shared__ float sm0[256], sm1[256];
    int tid = threadIdx.x;
    float s0 = 0.0f, s1 = 0.0f;
    for (int i = tid; i < HALF; i += 256) {
        s0 += g_rowloss[i];
        s1 += g_rowloss[HALF + i];
    }
    sm0[tid] = s0; sm1[tid] = s1;
    __syncthreads();
    for (int o = 128; o; o >>= 1) {
        if (tid < o) { sm0[tid] += sm0[tid + o]; sm1[tid] += sm1[tid + o]; }
        __syncthreads();
    }
    if (tid == 0)
        out[0] = 0.5f * (sm0[0] / (float)HALF + sm1[0] / (float)HALF);
}

// ============================================================
extern "C" void kernel_launch(void* const* d_in, const int* in_sizes, int n_in,
                              void* d_out, int out_size)
{
    const float* emb   = (const float*)d_in[0];
    const float* preds = (const float*)d_in[1];
    const float* queue = (const float*)d_in[2];
    float* out = (float*)d_out;

    __nv_bfloat16 *qhi, *phi;
    uint8_t *qf8, *ef8;
    cudaGetSymbolAddress((void**)&qhi, g_qhi);
    cudaGetSymbolAddress((void**)&phi, g_phi);
    cudaGetSymbolAddress((void**)&qf8, g_qf8);
    cudaGetSymbolAddress((void**)&ef8, g_ef8);

    queue_conv_kernel<<<(QTOT * DDIM / 4 + 255) / 256, 256>>>(queue, qhi, qf8, QTOT * DDIM / 4);
    emb_to_fp8_kernel<<<(B_TOT * DDIM / 4 + 255) / 256, 256>>>(emb, ef8, B_TOT * DDIM / 4);
    to_bf16_kernel<<<(B_TOT * DDIM / 4 + 255) / 256, 256>>>(preds, phi, B_TOT * DDIM / 4);

    const size_t smemArg = 1024 + 32768 + 65536;   // align + A + 2xB
    cudaFuncSetAttribute(argmax_mma_kernel,
                         cudaFuncAttributeMaxDynamicSharedMemorySize, (int)smemArg);
    argmax_mma_kernel<<<dim3(B_TOT / 128, QS), 512, smemArg>>>();

    rescore_kernel<<<B_TOT / 8, 256>>>(emb, queue);

    const size_t smemLog = 1024 + 65536 + 131072;
    cudaFuncSetAttribute(logits_mma_kernel,
                         cudaFuncAttributeMaxDynamicSharedMemorySize, (int)smemLog);
    logits_mma_kernel<<<dim3(HALF / 128, CS, 2), 256, smemLog>>>();

    ce_finalize_kernel<<<128, 256>>>(queue, preds);
    final_sum_kernel<<<1, 256>>>(out);
}

// round 13
// speedup vs baseline: 1.3838x; 1.3838x over previous
#include <cuda_runtime.h>
#include <cuda_bf16.h>
#include <math.h>
#include <stdint.h>

// NNclrInfoNCECriterion on GB300 (compute_103 PTX -> legacy mma.sync path).
// Stage 1: bf16 mma.sync sim GEMM, cheap tile-max epilogue -> thread top-2 ->
//          CTA top-4 -> exact fp32 rescore -> argmax.
// Stage 2: bf16 mma.sync logits GEMM + fp32 online LSE; exact fp32 diagonal.

#define B_TOT 4096
#define HALF  2048
#define DDIM  256
#define QTOT  65536
#define QS    32
#define QCHUNK (QTOT/QS)     // 2048
#define NTILE  (QCHUNK/128)  // 16 col-tiles per CTA
#define CS 4
#define NCOL (HALF/CS)       // 512
#define NTILE_LOG (NCOL/128) // 4
#define INV_T 10.0f
#define RS_MARGIN 0.02f

// ---------------- scratch globals ----------------
__device__ __nv_bfloat16 g_qhi[(size_t)QTOT * DDIM];
__device__ __nv_bfloat16 g_ehi[(size_t)B_TOT * DDIM];
__device__ __nv_bfloat16 g_phi[(size_t)B_TOT * DDIM];
__device__ float g_c4val[(size_t)B_TOT * 4 * QS];
__device__ int   g_c4idx[(size_t)B_TOT * 4 * QS];
__device__ int   g_gidx[B_TOT];
__device__ float g_lsem[2 * HALF * CS];
__device__ float g_lses[2 * HALF * CS];
__device__ float g_rowloss[2 * HALF];

// ---------------- helpers ----------------
__device__ __forceinline__ uint32_t smem_to_u32(const void* p) {
    uint32_t a;
    asm("{ .reg .u64 t; cvta.to.shared.u64 t, %1; cvt.u32.u64 %0, t; }" : "=r"(a) : "l"(p));
    return a;
}
__device__ __forceinline__ void cp_async16(uint32_t dst, const void* src) {
    asm volatile("cp.async.cg.shared.global [%0], [%1], 16;" :: "r"(dst), "l"(src) : "memory");
}
#define CP_COMMIT() asm volatile("cp.async.commit_group;" ::: "memory")
#define CP_WAIT0()  asm volatile("cp.async.wait_group 0;" ::: "memory")

__device__ __forceinline__ void ldsm_x4(uint32_t& r0, uint32_t& r1, uint32_t& r2, uint32_t& r3,
                                        uint32_t addr) {
    asm volatile("ldmatrix.sync.aligned.m8n8.x4.shared.b16 {%0,%1,%2,%3}, [%4];"
                 : "=r"(r0), "=r"(r1), "=r"(r2), "=r"(r3) : "r"(addr));
}
__device__ __forceinline__ void mma16816(float& d0, float& d1, float& d2, float& d3,
                                         uint32_t a0, uint32_t a1, uint32_t a2, uint32_t a3,
                                         uint32_t b0, uint32_t b1) {
    asm volatile("mma.sync.aligned.m16n8k16.row.col.f32.bf16.bf16.f32 "
                 "{%0,%1,%2,%3}, {%4,%5,%6,%7}, {%8,%9}, {%0,%1,%2,%3};"
                 : "+f"(d0), "+f"(d1), "+f"(d2), "+f"(d3)
                 : "r"(a0), "r"(a1), "r"(a2), "r"(a3), "r"(b0), "r"(b1));
}
// swizzled byte offset inside a [rows x 256 bf16] tile (512 B rows)
__device__ __forceinline__ uint32_t sw(uint32_t row, uint32_t kb) {
    return row * 512u + (kb ^ ((row & 7u) << 4));
}

// fragment loads for the 4x4 warp grid (warp tile 32 rows x 32 cols), one 16-k step
__device__ __forceinline__ void load_a_frags(uint32_t as32, int kf, int wm, int lane,
                                             uint32_t a[2][4]) {
    #pragma unroll
    for (int mi = 0; mi < 2; ++mi) {
        uint32_t row = (uint32_t)(wm * 32 + mi * 16 + (lane & 15));
        uint32_t kb  = (uint32_t)(kf * 32 + (lane >> 4) * 16);
        ldsm_x4(a[mi][0], a[mi][1], a[mi][2], a[mi][3], as32 + sw(row, kb));
    }
}
__device__ __forceinline__ void load_b_frags(uint32_t bbuf, int kf, int wn, int lane,
                                             uint32_t b[4][2]) {
    #pragma unroll
    for (int np = 0; np < 2; ++np) {
        uint32_t col = (uint32_t)(wn * 32 + np * 16 + (lane & 7) + ((lane >> 4) & 1) * 8);
        uint32_t kb  = (uint32_t)(kf * 32 + ((lane >> 3) & 1) * 16);
        uint32_t r0, r1, r2, r3;
        ldsm_x4(r0, r1, r2, r3, bbuf + sw(col, kb));
        b[2 * np][0] = r0; b[2 * np][1] = r1;
        b[2 * np + 1][0] = r2; b[2 * np + 1][1] = r3;
    }
}

// ============================================================
// fused fp32 -> bf16 conversion for queue, emb, preds
// ============================================================
__global__ void conv_all_kernel(const float* __restrict__ queue,
                                const float* __restrict__ emb,
                                const float* __restrict__ preds)
{
    const int nq = QTOT * DDIM / 4;
    const int ne = B_TOT * DDIM / 4;
    int i = blockIdx.x * blockDim.x + threadIdx.x;
    const float4* src;
    __nv_bfloat16* dst;
    int j;
    if (i < nq)               { src = (const float4*)queue; dst = g_qhi; j = i; }
    else if (i < nq + ne)     { src = (const float4*)emb;   dst = g_ehi; j = i - nq; }
    else if (i < nq + 2 * ne) { src = (const float4*)preds; dst = g_phi; j = i - nq - ne; }
    else return;
    float4 v = src[j];
    ((__nv_bfloat162*)dst)[2 * j]     = __floats2bfloat162_rn(v.x, v.y);
    ((__nv_bfloat162*)dst)[2 * j + 1] = __floats2bfloat162_rn(v.z, v.w);
}

// ============================================================
// Kernel 1: bf16 mma.sync sim GEMM + cheap tile-max top-2 epilogue.
// 512 threads, 16 warps (4x4 grid), warp tile 32x32, fragment double-buffer.
// CTA tile M=128 x N=128, K=256; A smem-resident, B double-buffered cp.async.
// ============================================================
__global__ __launch_bounds__(512, 1)
void argmax_mma_kernel()
{
    extern __shared__ char smem[];
    const uint32_t sb   = smem_to_u32(smem);
    const uint32_t as32 = (sb + 1023u) & ~1023u;   // A: 64KB
    const uint32_t bs32 = as32 + 65536u;           // B: 2 x 64KB

    const int tid  = threadIdx.x;
    const int lane = tid & 31;
    const int w    = tid >> 5;
    const int wm   = w >> 2;
    const int wn   = w & 3;
    const int rowBase = blockIdx.x * 128;
    const int qBase   = blockIdx.y * QCHUNK;

    // ---- async load A (128x256 bf16) + B tile 0 ----
    #pragma unroll
    for (int i = 0; i < 8; ++i) {
        int c = i * 512 + tid;
        uint32_t row = (uint32_t)(c >> 5), k16 = (uint32_t)(c & 31);
        cp_async16(as32 + sw(row, k16 * 16),
                   (const char*)(g_ehi + (size_t)(rowBase + row) * DDIM) + k16 * 16);
    }
    #pragma unroll
    for (int i = 0; i < 8; ++i) {
        int c = i * 512 + tid;
        uint32_t row = (uint32_t)(c >> 5), k16 = (uint32_t)(c & 31);
        cp_async16(bs32 + sw(row, k16 * 16),
                   (const char*)(g_qhi + (size_t)(qBase + row) * DDIM) + k16 * 16);
    }
    CP_COMMIT();
    CP_WAIT0();
    __syncthreads();

    float tv0[4], tv1[4];
    int   ti0[4], ti1[4];
    #pragma unroll
    for (int s = 0; s < 4; ++s) {
        tv0[s] = -INFINITY; tv1[s] = -INFINITY;
        ti0[s] = 0x7fffffff; ti1[s] = 0x7fffffff;
    }

    for (int ct = 0; ct < NTILE; ++ct) {
        // prefetch next B tile
        if (ct + 1 < NTILE) {
            const uint32_t nbuf = bs32 + (uint32_t)((ct + 1) & 1) * 65536u;
            #pragma unroll
            for (int i = 0; i < 8; ++i) {
                int c = i * 512 + tid;
                uint32_t row = (uint32_t)(c >> 5), k16 = (uint32_t)(c & 31);
                cp_async16(nbuf + sw(row, k16 * 16),
                           (const char*)(g_qhi + (size_t)(qBase + (ct + 1) * 128 + row) * DDIM) + k16 * 16);
            }
            CP_COMMIT();
        }

        const uint32_t bbuf = bs32 + (uint32_t)(ct & 1) * 65536u;
        float acc[2][4][4];
        #pragma unroll
        for (int mi = 0; mi < 2; ++mi)
            #pragma unroll
            for (int ni = 0; ni < 4; ++ni)
                #pragma unroll
                for (int d = 0; d < 4; ++d) acc[mi][ni][d] = 0.0f;

        // fragment double-buffer across the 16 k-steps
        uint32_t a[2][2][4], b[2][4][2];
        load_a_frags(as32, 0, wm, lane, a[0]);
        load_b_frags(bbuf, 0, wn, lane, b[0]);

        #pragma unroll
        for (int kf = 0; kf < 16; ++kf) {
            const int cur = kf & 1;
            if (kf < 15) {
                load_a_frags(as32, kf + 1, wm, lane, a[cur ^ 1]);
                load_b_frags(bbuf, kf + 1, wn, lane, b[cur ^ 1]);
            }
            #pragma unroll
            for (int mi = 0; mi < 2; ++mi)
                #pragma unroll
                for (int ni = 0; ni < 4; ++ni)
                    mma16816(acc[mi][ni][0], acc[mi][ni][1], acc[mi][ni][2], acc[mi][ni][3],
                             a[cur][mi][0], a[cur][mi][1], a[cur][mi][2], a[cur][mi][3],
                             b[cur][ni][0], b[cur][ni][1]);
        }

        // ---- cheap epilogue: fmax tree per slot, rare index scan ----
        const int colT = qBase + ct * 128 + wn * 32 + (lane & 3) * 2;
        #pragma unroll
        for (int s = 0; s < 4; ++s) {
            const int mi = s >> 1, dp = (s & 1) * 2;
            float m01 = fmaxf(acc[mi][0][dp], acc[mi][0][dp + 1]);
            float m23 = fmaxf(acc[mi][1][dp], acc[mi][1][dp + 1]);
            float m45 = fmaxf(acc[mi][2][dp], acc[mi][2][dp + 1]);
            float m67 = fmaxf(acc[mi][3][dp], acc[mi][3][dp + 1]);
            float m = fmaxf(fmaxf(m01, m23), fmaxf(m45, m67));
            if (m > tv1[s]) {
                // find first (lowest-col) element equal to m
                int c = -1;
                #pragma unroll
                for (int ni = 3; ni >= 0; --ni)
                    #pragma unroll
                    for (int q = 1; q >= 0; --q)
                        if (acc[mi][ni][dp + q] == m) c = colT + ni * 8 + q;
                if (m > tv0[s]) {
                    tv1[s] = tv0[s]; ti1[s] = ti0[s];
                    tv0[s] = m;      ti0[s] = c;
                } else {
                    tv1[s] = m;      ti1[s] = c;
                }
            }
        }

        CP_WAIT0();
        __syncthreads();
    }

    // ---- CTA top-4 reduce (reuse A smem): 16 contributors x 2 per row ----
    float* sval = (float*)(smem + (as32 - sb));
    int*   sidx = (int*)(sval + 128 * 32);
    const int own = wn * 4 + (lane & 3);
    #pragma unroll
    for (int s = 0; s < 4; ++s) {
        int rowL = wm * 32 + (s >> 1) * 16 + (s & 1) * 8 + (lane >> 2);
        sval[rowL * 32 + own * 2 + 0] = tv0[s];
        sval[rowL * 32 + own * 2 + 1] = tv1[s];
        sidx[rowL * 32 + own * 2 + 0] = ti0[s];
        sidx[rowL * 32 + own * 2 + 1] = ti1[s];
    }
    __syncthreads();
    if (tid < 128) {
        float t0 = -INFINITY, t1 = -INFINITY, t2 = -INFINITY, t3 = -INFINITY;
        int   j0 = 0x7fffffff, j1 = 0x7fffffff, j2 = 0x7fffffff, j3 = 0x7fffffff;
        #pragma unroll
        for (int t = 0; t < 32; ++t) {
            float v = sval[tid * 32 + t];
            int   i = sidx[tid * 32 + t];
            if (v > t0)      { t3=t2; j3=j2; t2=t1; j2=j1; t1=t0; j1=j0; t0=v; j0=i; }
            else if (v > t1) { t3=t2; j3=j2; t2=t1; j2=j1; t1=v; j1=i; }
            else if (v > t2) { t3=t2; j3=j2; t2=v; j2=i; }
            else if (v > t3) { t3=v; j3=i; }
        }
        size_t o = (size_t)(rowBase + tid) * (4 * QS) + blockIdx.y * 4;
        g_c4val[o + 0] = t0; g_c4idx[o + 0] = j0;
        g_c4val[o + 1] = t1; g_c4idx[o + 1] = j1;
        g_c4val[o + 2] = t2; g_c4idx[o + 2] = j2;
        g_c4val[o + 3] = t3; g_c4idx[o + 3] = j3;
    }
}

// ============================================================
// Kernel 2: exact fp32 rescore of 128 candidates -> g_gidx.
// ============================================================
__global__ void rescore_kernel(const float* __restrict__ emb,
                               const float* __restrict__ queue)
{
    int warp = (blockIdx.x * blockDim.x + threadIdx.x) >> 5;
    int lane = threadIdx.x & 31;
    if (warp >= B_TOT) return;

    size_t o = (size_t)warp * (4 * QS);
    float v[4]; int ix[4];
    #pragma unroll
    for (int j = 0; j < 4; ++j) {
        v[j]  = g_c4val[o + j * 32 + lane];
        ix[j] = g_c4idx[o + j * 32 + lane];
    }

    float m = fmaxf(fmaxf(v[0], v[1]), fmaxf(v[2], v[3]));
    #pragma unroll
    for (int sh = 16; sh; sh >>= 1) m = fmaxf(m, __shfl_xor_sync(0xffffffffu, m, sh));
    const float thr = m - RS_MARGIN;

    const float4* e4 = (const float4*)(emb + (size_t)warp * DDIM);
    float bv = -INFINITY; int bi = 0x7fffffff;
    #pragma unroll
    for (int j = 0; j < 4; ++j) {
        if (v[j] >= thr) {
            const float4* q4 = (const float4*)(queue + (size_t)ix[j] * DDIM);
            float acc = 0.0f;
            #pragma unroll 8
            for (int k = 0; k < 64; ++k) {
                float4 a = e4[k], b = q4[k];
                acc = fmaf(a.x, b.x, acc); acc = fmaf(a.y, b.y, acc);
                acc = fmaf(a.z, b.z, acc); acc = fmaf(a.w, b.w, acc);
            }
            if (acc > bv || (acc == bv && ix[j] < bi)) { bv = acc; bi = ix[j]; }
        }
    }
    #pragma unroll
    for (int sh = 16; sh; sh >>= 1) {
        float ov = __shfl_xor_sync(0xffffffffu, bv, sh);
        int   oi = __shfl_xor_sync(0xffffffffu, bi, sh);
        if (ov > bv || (ov == bv && oi < bi)) { bv = ov; bi = oi; }
    }
    if (lane == 0) g_gidx[warp] = bi;
}

// ============================================================
// Kernel 3: bf16 mma.sync logits GEMM + fp32 online logsumexp partials.
// grid (16 row-tiles, CS colgroups, 2 dirs); 256 thr, 8 warps (4x2), tile 32x64.
// ============================================================
__global__ __launch_bounds__(256, 1)
void logits_mma_kernel()
{
    extern __shared__ char smem[];
    const uint32_t sb   = smem_to_u32(smem);
    const uint32_t as32 = (sb + 1023u) & ~1023u;
    const uint32_t bs32 = as32 + 65536u;

    const int tid  = threadIdx.x;
    const int lane = tid & 31;
    const int w    = tid >> 5;
    const int wm   = w >> 1;
    const int wn   = w & 1;
    const int dir      = blockIdx.z;
    const int rowBase  = blockIdx.x * 128;
    const int colBase  = blockIdx.y * NCOL;
    const int predBase = (dir == 0) ? HALF : 0;
    const int idxBase  = dir * HALF;

    #pragma unroll
    for (int i = 0; i < 16; ++i) {
        int c = i * 256 + tid;
        uint32_t row = (uint32_t)(c >> 5), k16 = (uint32_t)(c & 31);
        int qi = g_gidx[idxBase + rowBase + (int)row];
        cp_async16(as32 + sw(row, k16 * 16),
                   (const char*)(g_qhi + (size_t)qi * DDIM) + k16 * 16);
    }
    #pragma unroll
    for (int i = 0; i < 16; ++i) {
        int c = i * 256 + tid;
        uint32_t row = (uint32_t)(c >> 5), k16 = (uint32_t)(c & 31);
        cp_async16(bs32 + sw(row, k16 * 16),
                   (const char*)(g_phi + (size_t)(predBase + colBase + row) * DDIM) + k16 * 16);
    }
    CP_COMMIT();
    CP_WAIT0();
    __syncthreads();

    float lm[4], ls[4];
    #pragma unroll
    for (int s = 0; s < 4; ++s) { lm[s] = -INFINITY; ls[s] = 0.0f; }

    for (int ct = 0; ct < NTILE_LOG; ++ct) {
        if (ct + 1 < NTILE_LOG) {
            const uint32_t nbuf = bs32 + (uint32_t)((ct + 1) & 1) * 65536u;
            #pragma unroll
            for (int i = 0; i < 16; ++i) {
                int c = i * 256 + tid;
                uint32_t row = (uint32_t)(c >> 5), k16 = (uint32_t)(c & 31);
                cp_async16(nbuf + sw(row, k16 * 16),
                           (const char*)(g_phi + (size_t)(predBase + colBase + (ct + 1) * 128 + row) * DDIM) + k16 * 16);
            }
            CP_COMMIT();
        }

        const uint32_t bbuf = bs32 + (uint32_t)(ct & 1) * 65536u;
        float acc[2][8][4];
        #pragma unroll
        for (int mi = 0; mi < 2; ++mi)
            #pragma unroll
            for (int ni = 0; ni < 8; ++ni)
                #pragma unroll
                for (int d = 0; d < 4; ++d) acc[mi][ni][d] = 0.0f;

        #pragma unroll
        for (int kf = 0; kf < 16; ++kf) {
            uint32_t a[2][4];
            #pragma unroll
            for (int mi = 0; mi < 2; ++mi) {
                uint32_t row = (uint32_t)(wm * 32 + mi * 16 + (lane & 15));
                uint32_t kb  = (uint32_t)(kf * 32 + (lane >> 4) * 16);
                ldsm_x4(a[mi][0], a[mi][1], a[mi][2], a[mi][3], as32 + sw(row, kb));
            }
            uint32_t b[8][2];
            #pragma unroll
            for (int np = 0; np < 4; ++np) {
                uint32_t col = (uint32_t)(wn * 64 + np * 16 + (lane & 7) + ((lane >> 4) & 1) * 8);
                uint32_t kb  = (uint32_t)(kf * 32 + ((lane >> 3) & 1) * 16);
                uint32_t r0, r1, r2, r3;
                ldsm_x4(r0, r1, r2, r3, bbuf + sw(col, kb));
                b[2 * np][0] = r0; b[2 * np][1] = r1;
                b[2 * np + 1][0] = r2; b[2 * np + 1][1] = r3;
            }
            #pragma unroll
            for (int mi = 0; mi < 2; ++mi)
                #pragma unroll
                for (int ni = 0; ni < 8; ++ni)
                    mma16816(acc[mi][ni][0], acc[mi][ni][1], acc[mi][ni][2], acc[mi][ni][3],
                             a[mi][0], a[mi][1], a[mi][2], a[mi][3], b[ni][0], b[ni][1]);
        }

        #pragma unroll
        for (int mi = 0; mi < 2; ++mi)
            #pragma unroll
            for (int ni = 0; ni < 8; ++ni)
                #pragma unroll
                for (int d = 0; d < 4; ++d) {
                    float x = acc[mi][ni][d] * INV_T;
                    int   s = mi * 2 + (d >> 1);
                    if (x > lm[s]) {
                        ls[s] = ls[s] * expf(lm[s] - x) + 1.0f;
                        lm[s] = x;
                    } else {
                        ls[s] += expf(x - lm[s]);
                    }
                }

        CP_WAIT0();
        __syncthreads();
    }

    float* sM = (float*)(smem + (as32 - sb));
    float* sS = sM + 128 * 8;
    const int cont = wn * 4 + (lane & 3);
    #pragma unroll
    for (int s = 0; s < 4; ++s) {
        int rowL = wm * 32 + (s >> 1) * 16 + (s & 1) * 8 + (lane >> 2);
        sM[rowL * 8 + cont] = lm[s];
        sS[rowL * 8 + cont] = ls[s];
    }
    __syncthreads();
    if (tid < 128) {
        float M = -INFINITY;
        #pragma unroll
        for (int t = 0; t < 8; ++t) M = fmaxf(M, sM[tid * 8 + t]);
        float S = 0.0f;
        #pragma unroll
        for (int t = 0; t < 8; ++t) S += sS[tid * 8 + t] * expf(sM[tid * 8 + t] - M);
        int row = rowBase + tid;
        g_lsem[(size_t)(idxBase + row) * CS + blockIdx.y] = M;
        g_lses[(size_t)(idxBase + row) * CS + blockIdx.y] = S;
    }
}

// ============================================================
// Kernel 4: per-row loss = logsumexp - exact fp32 diagonal logit.
// ============================================================
__global__ void ce_finalize_kernel(const float* __restrict__ queue,
                                   const float* __restrict__ preds)
{
    int warp = (blockIdx.x * blockDim.x + threadIdx.x) >> 5;
    int lane = threadIdx.x & 31;
    #pragma unroll
    for (int rr = 0; rr < 4; ++rr) {
        int ridx = warp * 4 + rr;
        if (ridx >= 2 * HALF) return;
        int dir = ridx >> 11;
        int row = ridx & (HALF - 1);
        int qi  = g_gidx[dir * HALF + row];
        const float* a = queue + (size_t)qi * DDIM;
        const float* b = preds + (size_t)(((dir == 0) ? HALF : 0) + row) * DDIM;
        float p = 0.0f;
        for (int k = lane; k < DDIM; k += 32) p = fmaf(a[k], b[k], p);
        #pragma unroll
        for (int o = 16; o; o >>= 1) p += __shfl_xor_sync(0xffffffffu, p, o);
        if (lane == 0) {
            float M = -INFINITY;
            #pragma unroll
            for (int t = 0; t < CS; ++t) M = fmaxf(M, g_lsem[(size_t)ridx * CS + t]);
            float S = 0.0f;
            #pragma unroll
            for (int t = 0; t < CS; ++t)
                S += g_lses[(size_t)ridx * CS + t] * expf(g_lsem[(size_t)ridx * CS + t] - M);
            float lse = M + logf(S);
            g_rowloss[ridx] = lse - p * INV_T;
        }
    }
}

// ============================================================
// Kernel 5: final reduction -> scalar loss
// ============================================================
__global__ void final_sum_kernel(float* __restrict__ out)
{
    __shared__ float sm0[256], sm1[256];
    int tid = threadIdx.x;
    float s0 = 0.0f, s1 = 0.0f;
    for (int i = tid; i < HALF; i += 256) {
        s0 += g_rowloss[i];
        s1 += g_rowloss[HALF + i];
    }
    sm0[tid] = s0; sm1[tid] = s1;
    __syncthreads();
    for (int o = 128; o; o >>= 1) {
        if (tid < o) { sm0[tid] += sm0[tid + o]; sm1[tid] += sm1[tid + o]; }
        __syncthreads();
    }
    if (tid == 0)
        out[0] = 0.5f * (sm0[0] / (float)HALF + sm1[0] / (float)HALF);
}

// ============================================================
extern "C" void kernel_launch(void* const* d_in, const int* in_sizes, int n_in,
                              void* d_out, int out_size)
{
    const float* emb   = (const float*)d_in[0];
    const float* preds = (const float*)d_in[1];
    const float* queue = (const float*)d_in[2];
    float* out = (float*)d_out;

    const int nConv = (QTOT + 2 * B_TOT) * DDIM / 4;
    conv_all_kernel<<<(nConv + 255) / 256, 256>>>(queue, emb, preds);

    const size_t smemArg = 1024 + 65536 + 131072;
    cudaFuncSetAttribute(argmax_mma_kernel,
                         cudaFuncAttributeMaxDynamicSharedMemorySize, (int)smemArg);
    argmax_mma_kernel<<<dim3(B_TOT / 128, QS), 512, smemArg>>>();

    rescore_kernel<<<B_TOT / 8, 256>>>(emb, queue);

    cudaFuncSetAttribute(logits_mma_kernel,
                         cudaFuncAttributeMaxDynamicSharedMemorySize, (int)smemArg);
    logits_mma_kernel<<<dim3(HALF / 128, CS, 2), 256, smemArg>>>();

    ce_finalize_kernel<<<128, 256>>>(queue, preds);
    final_sum_kernel<<<1, 256>>>(out);
}